// round 3
// baseline (speedup 1.0000x reference)
#include <cuda_runtime.h>
#include <cuda_bf16.h>

// GGMLLinear: out[o] = sum_k x[k] * scales[o, k/32] * q[o,k] + bias[o]
// x: [1, 4096] f32, q: [14336, 4096] int32 (int8-range), scales: [14336, 128] f32,
// bias: [14336] f32, out: [1, 14336] f32.
//
// Memory-bound GEMV (235MB of q per call). R3: revert to R1's proven shape
// (smem-staged x, __ldg q, unroll 8, 1 warp/row) with ONE change — halve the
// CTA grain (128 threads / 4 rows, grid=3584) to shrink the end-of-kernel
// imbalance tail (avg/max CTAs per SM: 24.2/25 vs 12.1/13) while keeping
// 48 resident warps/SM and identical per-warp code.

#define IN_DIM 4096
#define OUT_DIM 14336
#define NB (IN_DIM / 32)          // 128 scale blocks per row
#define ROWS_PER_CTA 4
#define THREADS 128

__global__ __launch_bounds__(THREADS)
void ggml_q8_gemv(const float* __restrict__ x,
                  const int* __restrict__ q,
                  const float* __restrict__ scales,
                  const float* __restrict__ bias,
                  float* __restrict__ out)
{
    __shared__ float xs[IN_DIM];

    // Stage x (16KB) into shared. 1024 float4 / 128 threads = 8 each.
    {
        const float4* x4 = reinterpret_cast<const float4*>(x);
        float4* xs4 = reinterpret_cast<float4*>(xs);
        #pragma unroll
        for (int i = threadIdx.x; i < IN_DIM / 4; i += THREADS)
            xs4[i] = x4[i];
    }
    __syncthreads();

    const int warp = threadIdx.x >> 5;
    const int lane = threadIdx.x & 31;
    const int row  = blockIdx.x * ROWS_PER_CTA + warp;   // grid sized exactly

    const int4*   qrow = reinterpret_cast<const int4*>(q + (size_t)row * IN_DIM);
    const float*  srow = scales + (size_t)row * NB;
    const float4* xs4  = reinterpret_cast<const float4*>(xs);

    float acc = 0.0f;

    // 1024 int4 per row / 32 lanes = 32 steps. idx4 = step*32 + lane.
    // scale index: (idx4*4)/32 = idx4 >> 3 (a 16B group never crosses a 32-block).
    #pragma unroll 8
    for (int it = 0; it < 32; ++it) {
        const int idx4 = it * 32 + lane;
        const int4   qv = __ldg(&qrow[idx4]);
        const float4 xv = xs4[idx4];
        const float  s  = __ldg(&srow[idx4 >> 3]);
        float dot = xv.x * (float)qv.x;
        dot = fmaf(xv.y, (float)qv.y, dot);
        dot = fmaf(xv.z, (float)qv.z, dot);
        dot = fmaf(xv.w, (float)qv.w, dot);
        acc = fmaf(s, dot, acc);
    }

    // Warp reduction
    #pragma unroll
    for (int off = 16; off > 0; off >>= 1)
        acc += __shfl_xor_sync(0xffffffffu, acc, off);

    if (lane == 0)
        out[row] = acc + __ldg(&bias[row]);
}

extern "C" void kernel_launch(void* const* d_in, const int* in_sizes, int n_in,
                              void* d_out, int out_size)
{
    const float* x      = (const float*)d_in[0];
    const int*   q      = (const int*)d_in[1];
    const float* scales = (const float*)d_in[2];
    const float* bias   = (const float*)d_in[3];
    float*       out    = (float*)d_out;

    const int grid = OUT_DIM / ROWS_PER_CTA;   // 3584
    ggml_q8_gemv<<<grid, THREADS>>>(x, q, scales, bias, out);
}

// round 5
// speedup vs baseline: 1.3271x; 1.3271x over previous
#include <cuda_runtime.h>
#include <cuda_bf16.h>

// GGMLLinear: out[o] = sum_k x[k] * scales[o, k/32] * q[o,k] + bias[o]
// x: [1, 4096] f32, q: [14336, 4096] int32 (int8-range), scales: [14336, 128] f32,
// bias: [14336] f32, out: [1, 14336] f32.
//
// Memory-bound GEMV (235MB q stream). R5 = R4 with the scale-shuffle FIXED:
//  - scales held strided across lanes (lane L: scale[L], [L+32], [L+64], [L+96]).
//    Iter `it`, lane L needs scale[4*it + (L>>3)] = reg (it>>3) of source lane
//    ((it&7)<<2) + (L>>3). One reg-select + one shfl per iter; no mainloop LDG.
//  - __launch_bounds__(256,5): reg cap 51 so ptxas can front-batch the
//    unroll-8 int4 q loads (payload alone = 32 regs) -> higher MLP_eff.

#define IN_DIM 4096
#define OUT_DIM 14336
#define NB (IN_DIM / 32)          // 128 scale blocks per row
#define ROWS_PER_CTA 8
#define THREADS 256

__global__ __launch_bounds__(THREADS, 5)
void ggml_q8_gemv(const float* __restrict__ x,
                  const int* __restrict__ q,
                  const float* __restrict__ scales,
                  const float* __restrict__ bias,
                  float* __restrict__ out)
{
    __shared__ float xs[IN_DIM];

    // Stage x (16KB) into shared. 1024 float4 / 256 threads = 4 each.
    {
        const float4* x4 = reinterpret_cast<const float4*>(x);
        float4* xs4 = reinterpret_cast<float4*>(xs);
        #pragma unroll
        for (int i = threadIdx.x; i < IN_DIM / 4; i += THREADS)
            xs4[i] = x4[i];
    }
    __syncthreads();

    const int warp = threadIdx.x >> 5;
    const int lane = threadIdx.x & 31;
    const int row  = blockIdx.x * ROWS_PER_CTA + warp;   // grid sized exactly

    const int4*   qrow = reinterpret_cast<const int4*>(q + (size_t)row * IN_DIM);
    const float4* xs4  = reinterpret_cast<const float4*>(xs);

    // Preload all 128 row scales, strided: lane L holds scale[L + 32*r].
    const float* srow = scales + (size_t)row * NB;
    const float s0 = __ldg(&srow[lane]);
    const float s1 = __ldg(&srow[lane + 32]);
    const float s2 = __ldg(&srow[lane + 64]);
    const float s3 = __ldg(&srow[lane + 96]);
    const int csel = lane >> 3;   // which of the 4 scale blocks in this 16B group

    float acc = 0.0f;

    // 1024 int4 per row / 32 lanes = 32 steps. idx4 = it*32 + lane.
    // Scale for iter it, lane L: scale[4*it + (L>>3)]
    //   = reg (it>>3) of lane ((it&7)*4 + (L>>3)).
    #pragma unroll 8
    for (int it = 0; it < 32; ++it) {
        const int idx4 = it * 32 + lane;
        const int4   qv = __ldg(&qrow[idx4]);
        const float4 xv = xs4[idx4];
        const float  sv = (it < 8) ? s0 : (it < 16) ? s1 : (it < 24) ? s2 : s3;
        const float  s  = __shfl_sync(0xffffffffu, sv, ((it & 7) << 2) + csel);
        float dot = xv.x * (float)qv.x;
        dot = fmaf(xv.y, (float)qv.y, dot);
        dot = fmaf(xv.z, (float)qv.z, dot);
        dot = fmaf(xv.w, (float)qv.w, dot);
        acc = fmaf(s, dot, acc);
    }

    // Warp reduction
    #pragma unroll
    for (int off = 16; off > 0; off >>= 1)
        acc += __shfl_xor_sync(0xffffffffu, acc, off);

    if (lane == 0)
        out[row] = acc + __ldg(&bias[row]);
}

extern "C" void kernel_launch(void* const* d_in, const int* in_sizes, int n_in,
                              void* d_out, int out_size)
{
    const float* x      = (const float*)d_in[0];
    const int*   q      = (const int*)d_in[1];
    const float* scales = (const float*)d_in[2];
    const float* bias   = (const float*)d_in[3];
    float*       out    = (float*)d_out;

    const int grid = OUT_DIM / ROWS_PER_CTA;   // 1792
    ggml_q8_gemv<<<grid, THREADS>>>(x, q, scales, bias, out);
}